// round 1
// baseline (speedup 1.0000x reference)
#include <cuda_runtime.h>

// ============================================================================
// Chamfer loss, brute force, f32x2-packed.
//   d^2(a,b) = |a|^2 + |b|^2 - 2 a.b = 2*( H_a + g ),  g = H_b - a.b, H = 0.5|p|^2
//   Inner loop per pair: g = fma(-ax, bx, fma(-ay, by, H_b)) then running min.
//   Packed over 2 target points via fma.rn.f32x2 -> 1 FFMA2 + 2 FMNMX / 2 pairs.
// ============================================================================

#define NMAX   16384
#define TPB    256
#define QPT    8              // queries per thread
#define BQ     (TPB * QPT)    // 2048 queries per block row
#define BPAIRS 64             // target pairs (128 points) per block chunk

__device__ __align__(16) float    g_PX[2][NMAX];
__device__ __align__(16) float    g_PY[2][NMAX];
__device__ __align__(16) float    g_PH[2][NMAX];
__device__              unsigned  g_UMIN[2][NMAX];

static __device__ __forceinline__ unsigned long long pk2(float lo, float hi) {
    unsigned long long r;
    asm("mov.b64 %0, {%1, %2};" : "=l"(r) : "f"(lo), "f"(hi));
    return r;
}
static __device__ __forceinline__ void upk2(unsigned long long v, float& lo, float& hi) {
    asm("mov.b64 {%0, %1}, %2;" : "=f"(lo), "=f"(hi) : "l"(v));
}
static __device__ __forceinline__ unsigned long long ffma2(
    unsigned long long a, unsigned long long b, unsigned long long c) {
    unsigned long long d;
    asm("fma.rn.f32x2 %0, %1, %2, %3;" : "=l"(d) : "l"(a), "l"(b), "l"(c));
    return d;
}

// Order-preserving float->uint map (works for negative g too).
static __device__ __forceinline__ unsigned f2ord(float f) {
    int b = __float_as_int(f);
    return (unsigned)b ^ (b < 0 ? 0xFFFFFFFFu : 0x80000000u);
}
static __device__ __forceinline__ float ord2f(unsigned u) {
    int b = (u & 0x80000000u) ? (int)(u ^ 0x80000000u) : (int)(~u);
    return __int_as_float(b);
}

// ---------------------------------------------------------------------------
// Kernel 0: precompute per-point (x, y, H=0.5*(x^2+y^2)), init mins, zero out.
// ---------------------------------------------------------------------------
__global__ void prep_kernel(const float* __restrict__ A, int na,
                            const float* __restrict__ B, int nb,
                            float* __restrict__ out) {
    int i = blockIdx.x * blockDim.x + threadIdx.x;
    if (i == 0) out[0] = 0.0f;
    if (i < na) {
        float x = A[2 * i], y = A[2 * i + 1];
        g_PX[0][i] = x; g_PY[0][i] = y;
        g_PH[0][i] = 0.5f * (x * x + y * y);
        g_UMIN[0][i] = 0xFFFFFFFFu;
    }
    if (i < nb) {
        float x = B[2 * i], y = B[2 * i + 1];
        g_PX[1][i] = x; g_PY[1][i] = y;
        g_PH[1][i] = 0.5f * (x * x + y * y);
        g_UMIN[1][i] = 0xFFFFFFFFu;
    }
}

// ---------------------------------------------------------------------------
// Kernel 1: brute-force min over target chunks. blockIdx.z = direction.
// Each thread: QPT queries (strided by TPB), streams BPAIRS packed targets.
// ---------------------------------------------------------------------------
__global__ __launch_bounds__(TPB) void chamfer_brute(int na, int nb) {
    const int dir  = blockIdx.z;
    const int qset = dir;
    const int tset = dir ^ 1;
    const int nq = (dir == 0) ? na : nb;
    const int nt = (dir == 0) ? nb : na;

    const int npairs = nt >> 1;
    const int jp0 = blockIdx.x * BPAIRS;
    if (jp0 >= npairs && !((nt & 1) && jp0 == npairs)) return;
    const int jpend = min(jp0 + BPAIRS, npairs);

    const int q0 = blockIdx.y * BQ + threadIdx.x;
    if (q0 >= nq) return;

    unsigned long long nax2[QPT], nay2[QPT];
    float rlo[QPT], rhi[QPT];
    const float INF = __int_as_float(0x7f800000);

#pragma unroll
    for (int k = 0; k < QPT; k++) {
        int q = q0 + k * TPB;
        float x = 0.f, y = 0.f;
        if (q < nq) { x = g_PX[qset][q]; y = g_PY[qset][q]; }
        nax2[k] = pk2(-x, -x);
        nay2[k] = pk2(-y, -y);
        rlo[k] = INF;
        rhi[k] = INF;
    }

    const unsigned long long* __restrict__ bxp =
        (const unsigned long long*)&g_PX[tset][0];
    const unsigned long long* __restrict__ byp =
        (const unsigned long long*)&g_PY[tset][0];
    const unsigned long long* __restrict__ chp =
        (const unsigned long long*)&g_PH[tset][0];

#pragma unroll 2
    for (int j = jp0; j < jpend; j++) {
        unsigned long long bx2 = __ldg(bxp + j);
        unsigned long long by2 = __ldg(byp + j);
        unsigned long long ch2 = __ldg(chp + j);
#pragma unroll
        for (int k = 0; k < QPT; k++) {
            unsigned long long v = ffma2(nax2[k], bx2, ffma2(nay2[k], by2, ch2));
            float vlo, vhi;
            upk2(v, vlo, vhi);
            rlo[k] = fminf(rlo[k], vlo);
            rhi[k] = fminf(rhi[k], vhi);
        }
    }

    // Odd-count tail target (not hit for nt=16384; kept for generality).
    if ((nt & 1) && (jpend == npairs) && (jp0 <= npairs)) {
        int last = nt - 1;
        float bx = g_PX[tset][last], by = g_PY[tset][last], ch = g_PH[tset][last];
#pragma unroll
        for (int k = 0; k < QPT; k++) {
            float nax, nay, dum;
            upk2(nax2[k], nax, dum);
            upk2(nay2[k], nay, dum);
            float v = fmaf(nax, bx, fmaf(nay, by, ch));
            rlo[k] = fminf(rlo[k], v);
        }
    }

#pragma unroll
    for (int k = 0; k < QPT; k++) {
        int q = q0 + k * TPB;
        if (q < nq) {
            float g = fminf(rlo[k], rhi[k]);
            atomicMin(&g_UMIN[qset][q], f2ord(g));   // compiles to REDG.MIN
        }
    }
}

// ---------------------------------------------------------------------------
// Kernel 2: d = sqrt(2*(H + g_min)); sum-reduce into out[0].
// ---------------------------------------------------------------------------
__global__ void finalize_kernel(int na, int nb, float* __restrict__ out) {
    int i = blockIdx.x * blockDim.x + threadIdx.x;
    int total = na + nb;
    float d = 0.f;
    if (i < total) {
        int set = (i < na) ? 0 : 1;
        int q   = (i < na) ? i : i - na;
        float g = ord2f(g_UMIN[set][q]);
        float d2 = 2.0f * (g_PH[set][q] + g);
        d = sqrtf(fmaxf(d2, 0.0f));
    }
#pragma unroll
    for (int off = 16; off > 0; off >>= 1)
        d += __shfl_down_sync(0xFFFFFFFFu, d, off);
    __shared__ float ws[TPB / 32];
    int lane = threadIdx.x & 31, wid = threadIdx.x >> 5;
    if (lane == 0) ws[wid] = d;
    __syncthreads();
    if (wid == 0) {
        d = (lane < TPB / 32) ? ws[lane] : 0.f;
#pragma unroll
        for (int off = 4; off > 0; off >>= 1)
            d += __shfl_down_sync(0xFFFFFFFFu, d, off);
        if (lane == 0) atomicAdd(out, d);
    }
}

// ---------------------------------------------------------------------------
extern "C" void kernel_launch(void* const* d_in, const int* in_sizes, int n_in,
                              void* d_out, int out_size) {
    const float* A = (const float*)d_in[0];   // img_render_points (flattened Nx2)
    const float* B = (const float*)d_in[1];   // ref cloud (Mx2)
    int na = in_sizes[0] / 2;
    int nb = in_sizes[1] / 2;
    float* out = (float*)d_out;

    int nmax = na > nb ? na : nb;
    prep_kernel<<<(nmax + TPB - 1) / TPB, TPB>>>(A, na, B, nb, out);

    int maxpairs = (nmax + 1) >> 1;
    dim3 grid((maxpairs + BPAIRS - 1) / BPAIRS, (nmax + BQ - 1) / BQ, 2);
    chamfer_brute<<<grid, TPB>>>(na, nb);

    int total = na + nb;
    finalize_kernel<<<(total + TPB - 1) / TPB, TPB>>>(na, nb, out);
}